// round 1
// baseline (speedup 1.0000x reference)
#include <cuda_runtime.h>
#include <cstdint>
#include <math.h>

#define NT 8192      // tokens = B*T
#define DD 1024      // model dim
#define FF 4096      // ffn dim
#define NE 8         // experts
#define BM 128
#define BN 64
#define BK 32
#define MAX_ROWS (NT*2 + NE*BM)   // 17408 (each expert segment padded to BM)
#define MT (MAX_ROWS/BM)          // 136 m-tiles

// Scratch (device globals: allocation-free, zero-initialized at load)
__device__ float g_h[(size_t)MAX_ROWS * FF];   // SwiGLU activations
__device__ int   g_perm[MAX_ROWS];             // assignment row -> token (-1 = pad)
__device__ float g_wt[MAX_ROWS];               // assignment row -> routing weight
__device__ int   g_counts[NE];
__device__ int   g_offs[NE + 1];               // padded segment offsets
__device__ int   g_cursor[NE];
__device__ int   g_eid[NT * 2];
__device__ float g_wr[NT * 2];

__device__ __forceinline__ uint32_t f2tf(float f) {
    uint32_t u;
    asm("cvt.rna.tf32.f32 %0, %1;" : "=r"(u) : "f"(f));
    return u;
}

__device__ __forceinline__ void mma_tf32(float c[4], const uint32_t a[4], const uint32_t b[2]) {
    asm volatile(
        "mma.sync.aligned.m16n8k8.row.col.f32.tf32.tf32.f32 "
        "{%0,%1,%2,%3}, {%4,%5,%6,%7}, {%8,%9}, {%0,%1,%2,%3};\n"
        : "+f"(c[0]), "+f"(c[1]), "+f"(c[2]), "+f"(c[3])
        : "r"(a[0]), "r"(a[1]), "r"(a[2]), "r"(a[3]), "r"(b[0]), "r"(b[1]));
}

// ---------------------------------------------------------------------------
__global__ void init_kernel(float* __restrict__ out) {
    int idx = blockIdx.x * blockDim.x + threadIdx.x;
    int stride = gridDim.x * blockDim.x;
    for (int i = idx; i < NT * DD; i += stride) out[i] = 0.f;
    for (int i = idx; i < MAX_ROWS; i += stride) g_perm[i] = -1;
    if (idx < NE) g_counts[idx] = 0;
}

// ---------------------------------------------------------------------------
// Router: 1 warp per token. logits = x @ gate_w ; top-2 ; renormalized softmax
// weights (full-softmax denominator cancels in the renormalization).
__global__ void router_kernel(const float* __restrict__ x, const float* __restrict__ gw) {
    int warp = (blockIdx.x * blockDim.x + threadIdx.x) >> 5;
    int lane = threadIdx.x & 31;
    if (warp >= NT) return;
    const float* xr = x + (size_t)warp * DD;
    float acc[NE];
#pragma unroll
    for (int e = 0; e < NE; e++) acc[e] = 0.f;
    for (int d = lane; d < DD; d += 32) {
        float xv = xr[d];
        const float* g = gw + d * NE;
#pragma unroll
        for (int e = 0; e < NE; e++) acc[e] += xv * g[e];
    }
#pragma unroll
    for (int e = 0; e < NE; e++) {
#pragma unroll
        for (int o = 16; o > 0; o >>= 1)
            acc[e] += __shfl_xor_sync(0xFFFFFFFFu, acc[e], o);
    }
    if (lane == 0) {
        int i0 = 0; float v0 = acc[0];
#pragma unroll
        for (int e = 1; e < NE; e++) if (acc[e] > v0) { v0 = acc[e]; i0 = e; }
        int i1 = -1; float v1 = -1e30f;
#pragma unroll
        for (int e = 0; e < NE; e++) {
            if (e == i0) continue;
            if (acc[e] > v1) { v1 = acc[e]; i1 = e; }
        }
        float e1 = expf(v1 - v0);
        float inv = 1.f / (1.f + e1);
        g_eid[2 * warp + 0] = i0; g_wr[2 * warp + 0] = inv;
        g_eid[2 * warp + 1] = i1; g_wr[2 * warp + 1] = e1 * inv;
        atomicAdd(&g_counts[i0], 1);
        atomicAdd(&g_counts[i1], 1);
    }
}

__global__ void offsets_kernel() {
    int acc = 0;
    for (int e = 0; e < NE; e++) {
        g_offs[e] = acc;
        g_cursor[e] = acc;
        acc += (g_counts[e] + BM - 1) / BM * BM;
    }
    g_offs[NE] = acc;
}

__global__ void scatter_kernel() {
    int t = blockIdx.x * blockDim.x + threadIdx.x;
    if (t >= NT) return;
#pragma unroll
    for (int k = 0; k < 2; k++) {
        int e = g_eid[2 * t + k];
        int pos = atomicAdd(&g_cursor[e], 1);
        g_perm[pos] = t;
        g_wt[pos] = g_wr[2 * t + k];
    }
}

// ---------------------------------------------------------------------------
// FFN1: h = silu(X @ W1[e]) * (X @ W3[e]) for gathered token rows.
// tf32 mma.sync m16n8k8; block tile 128x64, two B matrices share the A tile.
__global__ __launch_bounds__(256, 2) void ffn1_kernel(
    const float* __restrict__ x,
    const float* __restrict__ w1,
    const float* __restrict__ w3) {
    __shared__ uint32_t sA[BM][BK + 4];
    __shared__ uint32_t sB1[BK][BN + 4];
    __shared__ uint32_t sB3[BK][BN + 4];

    const int tm = blockIdx.y;
    const int n0 = blockIdx.x * BN;
    const int r0 = tm * BM;

    int e = NE - 1;
#pragma unroll
    for (int i = 0; i < NE; i++)
        if (r0 >= g_offs[i] && r0 < g_offs[i + 1]) e = i;

    const float* B1p = w1 + (size_t)e * DD * FF;
    const float* B3p = w3 + (size_t)e * DD * FF;

    const int tid = threadIdx.x;
    const int lane = tid & 31, warp = tid >> 5;
    const int wm = (warp >> 1) * 32, wn = (warp & 1) * 32;
    const int grp = lane >> 2, qid = lane & 3;

    float acc1[2][4][4], acc3[2][4][4];
#pragma unroll
    for (int mi = 0; mi < 2; mi++)
#pragma unroll
        for (int ni = 0; ni < 4; ni++)
#pragma unroll
            for (int t = 0; t < 4; t++) { acc1[mi][ni][t] = 0.f; acc3[mi][ni][t] = 0.f; }

    for (int k0 = 0; k0 < DD; k0 += BK) {
        // A tile: gathered token rows (zero-fill pad rows)
#pragma unroll
        for (int i = 0; i < 4; i++) {
            int idx = tid + i * 256;          // 0..1023 over 128 rows x 8 float4
            int row = idx >> 3, c4 = idx & 7;
            int p = g_perm[r0 + row];
            float4 v = make_float4(0.f, 0.f, 0.f, 0.f);
            if (p >= 0) v = *reinterpret_cast<const float4*>(x + (size_t)p * DD + k0 + c4 * 4);
            sA[row][c4 * 4 + 0] = f2tf(v.x);
            sA[row][c4 * 4 + 1] = f2tf(v.y);
            sA[row][c4 * 4 + 2] = f2tf(v.z);
            sA[row][c4 * 4 + 3] = f2tf(v.w);
        }
        // B tiles (w1, w3): [BK][BN]
#pragma unroll
        for (int i = 0; i < 2; i++) {
            int idx = tid + i * 256;          // 0..511 over 32 rows x 16 float4
            int kk = idx >> 4, c4 = idx & 15;
            const float4 v1 = *reinterpret_cast<const float4*>(B1p + (size_t)(k0 + kk) * FF + n0 + c4 * 4);
            const float4 v3 = *reinterpret_cast<const float4*>(B3p + (size_t)(k0 + kk) * FF + n0 + c4 * 4);
            sB1[kk][c4 * 4 + 0] = f2tf(v1.x);
            sB1[kk][c4 * 4 + 1] = f2tf(v1.y);
            sB1[kk][c4 * 4 + 2] = f2tf(v1.z);
            sB1[kk][c4 * 4 + 3] = f2tf(v1.w);
            sB3[kk][c4 * 4 + 0] = f2tf(v3.x);
            sB3[kk][c4 * 4 + 1] = f2tf(v3.y);
            sB3[kk][c4 * 4 + 2] = f2tf(v3.z);
            sB3[kk][c4 * 4 + 3] = f2tf(v3.w);
        }
        __syncthreads();
#pragma unroll
        for (int ks = 0; ks < BK; ks += 8) {
            uint32_t a[2][4];
#pragma unroll
            for (int mi = 0; mi < 2; mi++) {
                int rbase = wm + mi * 16 + grp;
                a[mi][0] = sA[rbase][ks + qid];
                a[mi][1] = sA[rbase + 8][ks + qid];
                a[mi][2] = sA[rbase][ks + qid + 4];
                a[mi][3] = sA[rbase + 8][ks + qid + 4];
            }
#pragma unroll
            for (int ni = 0; ni < 4; ni++) {
                int cb = wn + ni * 8 + grp;
                uint32_t b1[2], b3[2];
                b1[0] = sB1[ks + qid][cb]; b1[1] = sB1[ks + qid + 4][cb];
                b3[0] = sB3[ks + qid][cb]; b3[1] = sB3[ks + qid + 4][cb];
#pragma unroll
                for (int mi = 0; mi < 2; mi++) {
                    mma_tf32(acc1[mi][ni], a[mi], b1);
                    mma_tf32(acc3[mi][ni], a[mi], b3);
                }
            }
        }
        __syncthreads();
    }
    // Epilogue: SwiGLU -> h scratch (pad rows get zeros; harmless)
#pragma unroll
    for (int mi = 0; mi < 2; mi++)
#pragma unroll
        for (int ni = 0; ni < 4; ni++)
#pragma unroll
            for (int t = 0; t < 4; t++) {
                int row = r0 + wm + mi * 16 + grp + ((t >= 2) ? 8 : 0);
                int col = n0 + wn + ni * 8 + qid * 2 + (t & 1);
                float a = acc1[mi][ni][t];
                float s = a / (1.f + expf(-a));
                g_h[(size_t)row * FF + col] = s * acc3[mi][ni][t];
            }
}

// ---------------------------------------------------------------------------
// FFN2: out[token] += wt * (h @ W2[e]) with atomic scatter (2 adds/element).
__global__ __launch_bounds__(256, 2) void ffn2_kernel(
    const float* __restrict__ w2, float* __restrict__ out) {
    __shared__ uint32_t sA[BM][BK + 4];
    __shared__ uint32_t sB[BK][BN + 4];

    const int tm = blockIdx.y;
    const int n0 = blockIdx.x * BN;
    const int r0 = tm * BM;

    int e = NE - 1;
#pragma unroll
    for (int i = 0; i < NE; i++)
        if (r0 >= g_offs[i] && r0 < g_offs[i + 1]) e = i;

    const float* Bp = w2 + (size_t)e * FF * DD;

    const int tid = threadIdx.x;
    const int lane = tid & 31, warp = tid >> 5;
    const int wm = (warp >> 1) * 32, wn = (warp & 1) * 32;
    const int grp = lane >> 2, qid = lane & 3;

    float acc[2][4][4];
#pragma unroll
    for (int mi = 0; mi < 2; mi++)
#pragma unroll
        for (int ni = 0; ni < 4; ni++)
#pragma unroll
            for (int t = 0; t < 4; t++) acc[mi][ni][t] = 0.f;

    for (int k0 = 0; k0 < FF; k0 += BK) {
#pragma unroll
        for (int i = 0; i < 4; i++) {
            int idx = tid + i * 256;
            int row = idx >> 3, c4 = idx & 7;
            const float4 v = *reinterpret_cast<const float4*>(
                g_h + (size_t)(r0 + row) * FF + k0 + c4 * 4);
            sA[row][c4 * 4 + 0] = f2tf(v.x);
            sA[row][c4 * 4 + 1] = f2tf(v.y);
            sA[row][c4 * 4 + 2] = f2tf(v.z);
            sA[row][c4 * 4 + 3] = f2tf(v.w);
        }
#pragma unroll
        for (int i = 0; i < 2; i++) {
            int idx = tid + i * 256;
            int kk = idx >> 4, c4 = idx & 15;
            const float4 v = *reinterpret_cast<const float4*>(
                Bp + (size_t)(k0 + kk) * DD + n0 + c4 * 4);
            sB[kk][c4 * 4 + 0] = f2tf(v.x);
            sB[kk][c4 * 4 + 1] = f2tf(v.y);
            sB[kk][c4 * 4 + 2] = f2tf(v.z);
            sB[kk][c4 * 4 + 3] = f2tf(v.w);
        }
        __syncthreads();
#pragma unroll
        for (int ks = 0; ks < BK; ks += 8) {
            uint32_t a[2][4];
#pragma unroll
            for (int mi = 0; mi < 2; mi++) {
                int rbase = wm + mi * 16 + grp;
                a[mi][0] = sA[rbase][ks + qid];
                a[mi][1] = sA[rbase + 8][ks + qid];
                a[mi][2] = sA[rbase][ks + qid + 4];
                a[mi][3] = sA[rbase + 8][ks + qid + 4];
            }
#pragma unroll
            for (int ni = 0; ni < 4; ni++) {
                int cb = wn + ni * 8 + grp;
                uint32_t b[2];
                b[0] = sB[ks + qid][cb]; b[1] = sB[ks + qid + 4][cb];
#pragma unroll
                for (int mi = 0; mi < 2; mi++) mma_tf32(acc[mi][ni], a[mi], b);
            }
        }
        __syncthreads();
    }
#pragma unroll
    for (int mi = 0; mi < 2; mi++)
#pragma unroll
        for (int ni = 0; ni < 4; ni++)
#pragma unroll
            for (int t = 0; t < 4; t++) {
                int row = r0 + wm + mi * 16 + grp + ((t >= 2) ? 8 : 0);
                int p = g_perm[row];
                if (p >= 0) {
                    int col = n0 + wn + ni * 8 + qid * 2 + (t & 1);
                    atomicAdd(out + (size_t)p * DD + col, acc[mi][ni][t] * g_wt[row]);
                }
            }
}

// ---------------------------------------------------------------------------
extern "C" void kernel_launch(void* const* d_in, const int* in_sizes, int n_in,
                              void* d_out, int out_size) {
    const float* x  = (const float*)d_in[0];
    const float* gw = (const float*)d_in[1];
    const float* w1 = (const float*)d_in[2];
    const float* w3 = (const float*)d_in[3];
    const float* w2 = (const float*)d_in[4];
    float* out = (float*)d_out;

    init_kernel<<<4096, 256>>>(out);
    router_kernel<<<NT / 8, 256>>>(x, gw);
    offsets_kernel<<<1, 1>>>();
    scatter_kernel<<<(NT + 255) / 256, 256>>>();
    ffn1_kernel<<<dim3(FF / BN, MT), 256>>>(x, w1, w3);
    ffn2_kernel<<<dim3(DD / BN, MT), 256>>>(w2, out);
}

// round 2
// speedup vs baseline: 1.4200x; 1.4200x over previous
#include <cuda_runtime.h>
#include <cstdint>
#include <math.h>

#define NT 8192      // tokens = B*T
#define DD 1024      // model dim
#define FF 4096      // ffn dim
#define NE 8         // experts
#define BM 128
#define BK 32
#define BN1 64       // ffn1 N tile (x2 matrices)
#define BN2 128      // ffn2 N tile
#define MAX_ROWS (NT*2 + NE*BM)   // 17408
#define MT (MAX_ROWS/BM)          // 136 m-tiles
#define GROUP 16
#define MTP (((MT+GROUP-1)/GROUP)*GROUP)   // 144

// smem strides (floats); chosen for conflict-free banks + 16B cp.async alignment
#define SA_STRIDE 36           // bank = (4r+c)&31 : injective over (grp,qid)
#define SB1_STRIDE 72          // bank = (8r+c)&31 : injective over (qid,grp)
#define SB2_STRIDE 136
#define STA (BM*SA_STRIDE)     // 4608 floats per A stage
#define STB1 (BK*SB1_STRIDE)   // 2304 floats per B1 mat stage
#define STB2 (BK*SB2_STRIDE)   // 4352 floats per B2 stage
#define SMEM1_BYTES ((2*STA + 4*STB1) * 4)   // 73728
#define SMEM2_BYTES ((2*STA + 2*STB2) * 4)   // 71680

// Scratch (device globals: allocation-free)
__device__ float g_h[(size_t)MAX_ROWS * FF];
__device__ int   g_perm[MAX_ROWS];
__device__ float g_wt[MAX_ROWS];
__device__ int   g_counts[NE];
__device__ int   g_offs[NE + 1];
__device__ int   g_cursor[NE];
__device__ int   g_eid[NT * 2];
__device__ float g_wr[NT * 2];

__device__ __forceinline__ uint32_t f2tf(float f) {
    uint32_t u;
    asm("cvt.rna.tf32.f32 %0, %1;" : "=r"(u) : "f"(f));
    return u;
}

__device__ __forceinline__ void mma_tf32(float c[4], const uint32_t a[4], const uint32_t b[2]) {
    asm volatile(
        "mma.sync.aligned.m16n8k8.row.col.f32.tf32.tf32.f32 "
        "{%0,%1,%2,%3}, {%4,%5,%6,%7}, {%8,%9}, {%0,%1,%2,%3};\n"
        : "+f"(c[0]), "+f"(c[1]), "+f"(c[2]), "+f"(c[3])
        : "r"(a[0]), "r"(a[1]), "r"(a[2]), "r"(a[3]), "r"(b[0]), "r"(b[1]));
}

__device__ __forceinline__ void cp16(uint32_t smem_addr, const void* gptr, bool pred) {
    int sz = pred ? 16 : 0;
    asm volatile("cp.async.cg.shared.global [%0], [%1], 16, %2;\n"
                 :: "r"(smem_addr), "l"(gptr), "r"(sz));
}
__device__ __forceinline__ void cp_commit() {
    asm volatile("cp.async.commit_group;\n");
}

// ---------------------------------------------------------------------------
__global__ void init_kernel(float* __restrict__ out) {
    int idx = blockIdx.x * blockDim.x + threadIdx.x;
    int stride = gridDim.x * blockDim.x;
    for (int i = idx; i < NT * DD; i += stride) out[i] = 0.f;
    for (int i = idx; i < MAX_ROWS; i += stride) g_perm[i] = -1;
    if (idx < NE) g_counts[idx] = 0;
}

// ---------------------------------------------------------------------------
__global__ void router_kernel(const float* __restrict__ x, const float* __restrict__ gw) {
    int warp = (blockIdx.x * blockDim.x + threadIdx.x) >> 5;
    int lane = threadIdx.x & 31;
    if (warp >= NT) return;
    const float* xr = x + (size_t)warp * DD;
    float acc[NE];
#pragma unroll
    for (int e = 0; e < NE; e++) acc[e] = 0.f;
    for (int d = lane; d < DD; d += 32) {
        float xv = xr[d];
        const float* g = gw + d * NE;
#pragma unroll
        for (int e = 0; e < NE; e++) acc[e] += xv * g[e];
    }
#pragma unroll
    for (int e = 0; e < NE; e++) {
#pragma unroll
        for (int o = 16; o > 0; o >>= 1)
            acc[e] += __shfl_xor_sync(0xFFFFFFFFu, acc[e], o);
    }
    if (lane == 0) {
        int i0 = 0; float v0 = acc[0];
#pragma unroll
        for (int e = 1; e < NE; e++) if (acc[e] > v0) { v0 = acc[e]; i0 = e; }
        int i1 = -1; float v1 = -1e30f;
#pragma unroll
        for (int e = 0; e < NE; e++) {
            if (e == i0) continue;
            if (acc[e] > v1) { v1 = acc[e]; i1 = e; }
        }
        float e1 = expf(v1 - v0);
        float inv = 1.f / (1.f + e1);
        g_eid[2 * warp + 0] = i0; g_wr[2 * warp + 0] = inv;
        g_eid[2 * warp + 1] = i1; g_wr[2 * warp + 1] = e1 * inv;
        atomicAdd(&g_counts[i0], 1);
        atomicAdd(&g_counts[i1], 1);
    }
}

__global__ void offsets_kernel() {
    int acc = 0;
    for (int e = 0; e < NE; e++) {
        g_offs[e] = acc;
        g_cursor[e] = acc;
        acc += (g_counts[e] + BM - 1) / BM * BM;
    }
    g_offs[NE] = acc;
}

__global__ void scatter_kernel() {
    int t = blockIdx.x * blockDim.x + threadIdx.x;
    if (t >= NT) return;
#pragma unroll
    for (int k = 0; k < 2; k++) {
        int e = g_eid[2 * t + k];
        int pos = atomicAdd(&g_cursor[e], 1);
        g_perm[pos] = t;
        g_wt[pos] = g_wr[2 * t + k];
    }
}

// ---------------------------------------------------------------------------
// FFN1: h = silu(X @ W1[e]) * (X @ W3[e]). cp.async 2-stage pipeline,
// block-swizzled grid for L2 weight reuse, tf32 mma.sync.
__global__ __launch_bounds__(256, 2) void ffn1_kernel(
    const float* __restrict__ x,
    const float* __restrict__ w1,
    const float* __restrict__ w3) {
    extern __shared__ float smem[];
    float* sA = smem;                 // [2][BM][SA_STRIDE]
    float* sB = smem + 2 * STA;       // [2][2][BK][SB1_STRIDE]

    // block swizzle: strips of GROUP m-tiles; within strip, tm varies fastest
    const int NBT = FF / BN1;  // 64
    int bid = blockIdx.x;
    int strip = bid / (GROUP * NBT);
    int rem = bid % (GROUP * NBT);
    int tm = strip * GROUP + (rem % GROUP);
    int nb = rem / GROUP;
    if (tm >= MT) return;
    const int r0 = tm * BM;
    const int n0 = nb * BN1;
    if (r0 >= g_offs[NE]) return;     // past last padded segment

    int e = NE - 1;
#pragma unroll
    for (int i = 0; i < NE; i++)
        if (r0 >= g_offs[i] && r0 < g_offs[i + 1]) e = i;

    const float* B1p = w1 + (size_t)e * DD * FF;
    const float* B3p = w3 + (size_t)e * DD * FF;

    const int tid = threadIdx.x;
    const int lane = tid & 31, warp = tid >> 5;
    const int wm = (warp >> 1) * 32, wn = (warp & 1) * 32;
    const int grp = lane >> 2, qid = lane & 3;

    // cache perm for this thread's 4 A-load rows
    int pr[4];
#pragma unroll
    for (int i = 0; i < 4; i++) pr[i] = g_perm[r0 + (tid >> 3) + 32 * i];
    const int acol = (tid & 7) * 4;

    uint32_t sA_base = (uint32_t)__cvta_generic_to_shared(sA);
    uint32_t sB_base = (uint32_t)__cvta_generic_to_shared(sB);

    float acc1[2][4][4], acc3[2][4][4];
#pragma unroll
    for (int mi = 0; mi < 2; mi++)
#pragma unroll
        for (int ni = 0; ni < 4; ni++)
#pragma unroll
            for (int t = 0; t < 4; t++) { acc1[mi][ni][t] = 0.f; acc3[mi][ni][t] = 0.f; }

    const int NK = DD / BK;  // 32

    // ---- stage loader ----
    auto load_stage = [&](int st, int k0) {
#pragma unroll
        for (int i = 0; i < 4; i++) {
            int row = (tid >> 3) + 32 * i;
            int p = pr[i];
            const float* src = x + (size_t)(p < 0 ? 0 : p) * DD + k0 + acol;
            cp16(sA_base + (st * STA + row * SA_STRIDE + acol) * 4, src, p >= 0);
        }
#pragma unroll
        for (int i = 0; i < 4; i++) {
            int idx = tid + i * 256;           // 0..1023
            int mat = idx >> 9;                // 0/1
            int r = (idx >> 4) & 31;
            int c4 = (idx & 15) * 4;
            const float* src = (mat ? B3p : B1p) + (size_t)(k0 + r) * FF + n0 + c4;
            cp16(sB_base + (((st * 2 + mat) * STB1) + r * SB1_STRIDE + c4) * 4, src, true);
        }
        cp_commit();
    };

    load_stage(0, 0);

    for (int k = 0; k < NK; k++) {
        int st = k & 1;
        if (k + 1 < NK) {
            load_stage(st ^ 1, (k + 1) * BK);
            asm volatile("cp.async.wait_group 1;\n");
        } else {
            asm volatile("cp.async.wait_group 0;\n");
        }
        __syncthreads();

        const float* A = sA + st * STA;
        const float* B1s = sB + (st * 2 + 0) * STB1;
        const float* B3s = sB + (st * 2 + 1) * STB1;
#pragma unroll
        for (int ks = 0; ks < BK; ks += 8) {
            uint32_t a[2][4];
#pragma unroll
            for (int mi = 0; mi < 2; mi++) {
                int rb = wm + mi * 16 + grp;
                a[mi][0] = f2tf(A[rb * SA_STRIDE + ks + qid]);
                a[mi][1] = f2tf(A[(rb + 8) * SA_STRIDE + ks + qid]);
                a[mi][2] = f2tf(A[rb * SA_STRIDE + ks + qid + 4]);
                a[mi][3] = f2tf(A[(rb + 8) * SA_STRIDE + ks + qid + 4]);
            }
#pragma unroll
            for (int ni = 0; ni < 4; ni++) {
                int cb = wn + ni * 8 + grp;
                uint32_t b1[2], b3[2];
                b1[0] = f2tf(B1s[(ks + qid) * SB1_STRIDE + cb]);
                b1[1] = f2tf(B1s[(ks + qid + 4) * SB1_STRIDE + cb]);
                b3[0] = f2tf(B3s[(ks + qid) * SB1_STRIDE + cb]);
                b3[1] = f2tf(B3s[(ks + qid + 4) * SB1_STRIDE + cb]);
#pragma unroll
                for (int mi = 0; mi < 2; mi++) {
                    mma_tf32(acc1[mi][ni], a[mi], b1);
                    mma_tf32(acc3[mi][ni], a[mi], b3);
                }
            }
        }
        __syncthreads();
    }

    // Epilogue: SwiGLU, pre-rounded to tf32 so ffn2 skips A-fragment cvt
#pragma unroll
    for (int mi = 0; mi < 2; mi++)
#pragma unroll
        for (int ni = 0; ni < 4; ni++)
#pragma unroll
            for (int t = 0; t < 4; t++) {
                int row = r0 + wm + mi * 16 + grp + ((t >= 2) ? 8 : 0);
                int col = n0 + wn + ni * 8 + qid * 2 + (t & 1);
                float a = acc1[mi][ni][t];
                float s = a / (1.f + expf(-a));
                g_h[(size_t)row * FF + col] = __uint_as_float(f2tf(s * acc3[mi][ni][t]));
            }
}

// ---------------------------------------------------------------------------
// FFN2: out[token] += wt * (h @ W2[e]); BN=128, cp.async pipeline, atomics.
__global__ __launch_bounds__(256, 2) void ffn2_kernel(
    const float* __restrict__ w2, float* __restrict__ out) {
    extern __shared__ float smem[];
    float* sA = smem;                 // [2][BM][SA_STRIDE]
    float* sB = smem + 2 * STA;       // [2][BK][SB2_STRIDE]

    const int NBT = DD / BN2;  // 8
    int bid = blockIdx.x;
    int strip = bid / (GROUP * NBT);
    int rem = bid % (GROUP * NBT);
    int tm = strip * GROUP + (rem % GROUP);
    int nb = rem / GROUP;
    if (tm >= MT) return;
    const int r0 = tm * BM;
    const int n0 = nb * BN2;
    if (r0 >= g_offs[NE]) return;

    int e = NE - 1;
#pragma unroll
    for (int i = 0; i < NE; i++)
        if (r0 >= g_offs[i] && r0 < g_offs[i + 1]) e = i;

    const float* Bp = w2 + (size_t)e * FF * DD;

    const int tid = threadIdx.x;
    const int lane = tid & 31, warp = tid >> 5;
    const int wm = (warp >> 1) * 32, wn = (warp & 1) * 64;
    const int grp = lane >> 2, qid = lane & 3;
    const int acol = (tid & 7) * 4;

    uint32_t sA_base = (uint32_t)__cvta_generic_to_shared(sA);
    uint32_t sB_base = (uint32_t)__cvta_generic_to_shared(sB);

    float acc[2][8][4];
#pragma unroll
    for (int mi = 0; mi < 2; mi++)
#pragma unroll
        for (int ni = 0; ni < 8; ni++)
#pragma unroll
            for (int t = 0; t < 4; t++) acc[mi][ni][t] = 0.f;

    const int NK = FF / BK;  // 128

    auto load_stage = [&](int st, int k0) {
#pragma unroll
        for (int i = 0; i < 4; i++) {
            int row = (tid >> 3) + 32 * i;
            const float* src = g_h + (size_t)(r0 + row) * FF + k0 + acol;
            cp16(sA_base + (st * STA + row * SA_STRIDE + acol) * 4, src, true);
        }
#pragma unroll
        for (int i = 0; i < 4; i++) {
            int idx = tid + i * 256;           // 0..1023
            int r = idx >> 5;
            int c4 = (idx & 31) * 4;
            const float* src = Bp + (size_t)(k0 + r) * DD + n0 + c4;
            cp16(sB_base + (st * STB2 + r * SB2_STRIDE + c4) * 4, src, true);
        }
        cp_commit();
    };

    load_stage(0, 0);

    for (int k = 0; k < NK; k++) {
        int st = k & 1;
        if (k + 1 < NK) {
            load_stage(st ^ 1, (k + 1) * BK);
            asm volatile("cp.async.wait_group 1;\n");
        } else {
            asm volatile("cp.async.wait_group 0;\n");
        }
        __syncthreads();

        const float* A = sA + st * STA;
        const float* Bs = sB + st * STB2;
#pragma unroll
        for (int ks = 0; ks < BK; ks += 8) {
            uint32_t a[2][4];
#pragma unroll
            for (int mi = 0; mi < 2; mi++) {
                int rb = wm + mi * 16 + grp;
                // g_h was stored pre-rounded to tf32: use raw bits directly
                a[mi][0] = __float_as_uint(A[rb * SA_STRIDE + ks + qid]);
                a[mi][1] = __float_as_uint(A[(rb + 8) * SA_STRIDE + ks + qid]);
                a[mi][2] = __float_as_uint(A[rb * SA_STRIDE + ks + qid + 4]);
                a[mi][3] = __float_as_uint(A[(rb + 8) * SA_STRIDE + ks + qid + 4]);
            }
#pragma unroll
            for (int ni = 0; ni < 8; ni++) {
                int cb = wn + ni * 8 + grp;
                uint32_t b[2];
                b[0] = f2tf(Bs[(ks + qid) * SB2_STRIDE + cb]);
                b[1] = f2tf(Bs[(ks + qid + 4) * SB2_STRIDE + cb]);
#pragma unroll
                for (int mi = 0; mi < 2; mi++) mma_tf32(acc[mi][ni], a[mi], b);
            }
        }
        __syncthreads();
    }

#pragma unroll
    for (int mi = 0; mi < 2; mi++) {
#pragma unroll
        for (int t2 = 0; t2 < 2; t2++) {
            int row = r0 + wm + mi * 16 + grp + t2 * 8;
            int p = g_perm[row];
            if (p < 0) continue;
            float w = g_wt[row];
#pragma unroll
            for (int ni = 0; ni < 8; ni++) {
#pragma unroll
                for (int t = 0; t < 2; t++) {
                    int col = n0 + wn + ni * 8 + qid * 2 + t;
                    atomicAdd(out + (size_t)p * DD + col, acc[mi][ni][t2 * 2 + t] * w);
                }
            }
        }
    }
}

// ---------------------------------------------------------------------------
extern "C" void kernel_launch(void* const* d_in, const int* in_sizes, int n_in,
                              void* d_out, int out_size) {
    const float* x  = (const float*)d_in[0];
    const float* gw = (const float*)d_in[1];
    const float* w1 = (const float*)d_in[2];
    const float* w3 = (const float*)d_in[3];
    const float* w2 = (const float*)d_in[4];
    float* out = (float*)d_out;

    cudaFuncSetAttribute(ffn1_kernel, cudaFuncAttributeMaxDynamicSharedMemorySize, SMEM1_BYTES);
    cudaFuncSetAttribute(ffn2_kernel, cudaFuncAttributeMaxDynamicSharedMemorySize, SMEM2_BYTES);

    init_kernel<<<4096, 256>>>(out);
    router_kernel<<<NT / 8, 256>>>(x, gw);
    offsets_kernel<<<1, 1>>>();
    scatter_kernel<<<(NT + 255) / 256, 256>>>();
    ffn1_kernel<<<MTP * (FF / BN1), 256, SMEM1_BYTES>>>(x, w1, w3);
    ffn2_kernel<<<MTP * (DD / BN2), 256, SMEM2_BYTES>>>(w2, out);
}

// round 3
// speedup vs baseline: 1.4219x; 1.0013x over previous
#include <cuda_runtime.h>
#include <cstdint>
#include <math.h>

#define NT 8192      // tokens = B*T
#define DD 1024      // model dim
#define FF 4096      // ffn dim
#define NE 8         // experts
#define BM 128
#define BK 32
#define BN1 64       // ffn1 N tile (x2 matrices)
#define BN2 128      // ffn2 N tile
#define MAX_ROWS (NT*2 + NE*BM)   // 17408
#define MT (MAX_ROWS/BM)          // 136 m-tiles
#define GROUP 16
#define MTP (((MT+GROUP-1)/GROUP)*GROUP)   // 144

// smem strides (floats); chosen for conflict-free banks + 16B cp.async alignment
#define SA_STRIDE 36           // bank = (4r+c)&31 : injective over (grp,qid)
#define SB1_STRIDE 72          // bank = (8r+c)&31 : injective over (qid,grp)
#define SB2_STRIDE 136
#define STA (BM*SA_STRIDE)     // 4608 floats per A stage
#define STB1 (BK*SB1_STRIDE)   // 2304 floats per B1 mat stage
#define STB2 (BK*SB2_STRIDE)   // 4352 floats per B2 stage
#define SMEM1_BYTES ((2*STA + 4*STB1) * 4)   // 73728
#define SMEM2_BYTES ((2*STA + 2*STB2) * 4)   // 71680

// Scratch (device globals: allocation-free)
__device__ float g_h[(size_t)MAX_ROWS * FF];
__device__ int   g_perm[MAX_ROWS];
__device__ float g_wt[MAX_ROWS];
__device__ int   g_counts[NE];
__device__ int   g_offs[NE + 1];
__device__ int   g_cursor[NE];
__device__ int   g_eid[NT * 2];
__device__ float g_wr[NT * 2];

__device__ __forceinline__ uint32_t f2tf(float f) {
    uint32_t u;
    asm("cvt.rna.tf32.f32 %0, %1;" : "=r"(u) : "f"(f));
    return u;
}

__device__ __forceinline__ void mma_tf32(float c[4], const uint32_t a[4], const uint32_t b[2]) {
    asm volatile(
        "mma.sync.aligned.m16n8k8.row.col.f32.tf32.tf32.f32 "
        "{%0,%1,%2,%3}, {%4,%5,%6,%7}, {%8,%9}, {%0,%1,%2,%3};\n"
        : "+f"(c[0]), "+f"(c[1]), "+f"(c[2]), "+f"(c[3])
        : "r"(a[0]), "r"(a[1]), "r"(a[2]), "r"(a[3]), "r"(b[0]), "r"(b[1]));
}

__device__ __forceinline__ void cp16(uint32_t smem_addr, const void* gptr, bool pred) {
    int sz = pred ? 16 : 0;
    asm volatile("cp.async.cg.shared.global [%0], [%1], 16, %2;\n"
                 :: "r"(smem_addr), "l"(gptr), "r"(sz));
}
__device__ __forceinline__ void cp_commit() {
    asm volatile("cp.async.commit_group;\n");
}

// ---------------------------------------------------------------------------
__global__ void init_kernel(float* __restrict__ out) {
    int idx = blockIdx.x * blockDim.x + threadIdx.x;
    int stride = gridDim.x * blockDim.x;
    for (int i = idx; i < NT * DD; i += stride) out[i] = 0.f;
    for (int i = idx; i < MAX_ROWS; i += stride) g_perm[i] = -1;
    if (idx < NE) g_counts[idx] = 0;
}

// ---------------------------------------------------------------------------
__global__ void router_kernel(const float* __restrict__ x, const float* __restrict__ gw) {
    int warp = (blockIdx.x * blockDim.x + threadIdx.x) >> 5;
    int lane = threadIdx.x & 31;
    if (warp >= NT) return;
    const float* xr = x + (size_t)warp * DD;
    float acc[NE];
#pragma unroll
    for (int e = 0; e < NE; e++) acc[e] = 0.f;
    for (int d = lane; d < DD; d += 32) {
        float xv = xr[d];
        const float* g = gw + d * NE;
#pragma unroll
        for (int e = 0; e < NE; e++) acc[e] += xv * g[e];
    }
#pragma unroll
    for (int e = 0; e < NE; e++) {
#pragma unroll
        for (int o = 16; o > 0; o >>= 1)
            acc[e] += __shfl_xor_sync(0xFFFFFFFFu, acc[e], o);
    }
    if (lane == 0) {
        int i0 = 0; float v0 = acc[0];
#pragma unroll
        for (int e = 1; e < NE; e++) if (acc[e] > v0) { v0 = acc[e]; i0 = e; }
        int i1 = -1; float v1 = -1e30f;
#pragma unroll
        for (int e = 0; e < NE; e++) {
            if (e == i0) continue;
            if (acc[e] > v1) { v1 = acc[e]; i1 = e; }
        }
        float e1 = expf(v1 - v0);
        float inv = 1.f / (1.f + e1);
        g_eid[2 * warp + 0] = i0; g_wr[2 * warp + 0] = inv;
        g_eid[2 * warp + 1] = i1; g_wr[2 * warp + 1] = e1 * inv;
        atomicAdd(&g_counts[i0], 1);
        atomicAdd(&g_counts[i1], 1);
    }
}

__global__ void offsets_kernel() {
    int acc = 0;
    for (int e = 0; e < NE; e++) {
        g_offs[e] = acc;
        g_cursor[e] = acc;
        acc += (g_counts[e] + BM - 1) / BM * BM;
    }
    g_offs[NE] = acc;
}

__global__ void scatter_kernel() {
    int t = blockIdx.x * blockDim.x + threadIdx.x;
    if (t >= NT) return;
#pragma unroll
    for (int k = 0; k < 2; k++) {
        int e = g_eid[2 * t + k];
        int pos = atomicAdd(&g_cursor[e], 1);
        g_perm[pos] = t;
        g_wt[pos] = g_wr[2 * t + k];
    }
}

// ---------------------------------------------------------------------------
// FFN1: h = silu(X @ W1[e]) * (X @ W3[e]). cp.async 2-stage pipeline,
// block-swizzled grid for L2 weight reuse, tf32 mma.sync.
__global__ __launch_bounds__(256, 2) void ffn1_kernel(
    const float* __restrict__ x,
    const float* __restrict__ w1,
    const float* __restrict__ w3) {
    extern __shared__ float smem[];
    float* sA = smem;                 // [2][BM][SA_STRIDE]
    float* sB = smem + 2 * STA;       // [2][2][BK][SB1_STRIDE]

    // block swizzle: strips of GROUP m-tiles; within strip, tm varies fastest
    const int NBT = FF / BN1;  // 64
    int bid = blockIdx.x;
    int strip = bid / (GROUP * NBT);
    int rem = bid % (GROUP * NBT);
    int tm = strip * GROUP + (rem % GROUP);
    int nb = rem / GROUP;
    if (tm >= MT) return;
    const int r0 = tm * BM;
    const int n0 = nb * BN1;
    if (r0 >= g_offs[NE]) return;     // past last padded segment

    int e = NE - 1;
#pragma unroll
    for (int i = 0; i < NE; i++)
        if (r0 >= g_offs[i] && r0 < g_offs[i + 1]) e = i;

    const float* B1p = w1 + (size_t)e * DD * FF;
    const float* B3p = w3 + (size_t)e * DD * FF;

    const int tid = threadIdx.x;
    const int lane = tid & 31, warp = tid >> 5;
    const int wm = (warp >> 1) * 32, wn = (warp & 1) * 32;
    const int grp = lane >> 2, qid = lane & 3;

    // cache perm for this thread's 4 A-load rows
    int pr[4];
#pragma unroll
    for (int i = 0; i < 4; i++) pr[i] = g_perm[r0 + (tid >> 3) + 32 * i];
    const int acol = (tid & 7) * 4;

    uint32_t sA_base = (uint32_t)__cvta_generic_to_shared(sA);
    uint32_t sB_base = (uint32_t)__cvta_generic_to_shared(sB);

    float acc1[2][4][4], acc3[2][4][4];
#pragma unroll
    for (int mi = 0; mi < 2; mi++)
#pragma unroll
        for (int ni = 0; ni < 4; ni++)
#pragma unroll
            for (int t = 0; t < 4; t++) { acc1[mi][ni][t] = 0.f; acc3[mi][ni][t] = 0.f; }

    const int NK = DD / BK;  // 32

    // ---- stage loader ----
    auto load_stage = [&](int st, int k0) {
#pragma unroll
        for (int i = 0; i < 4; i++) {
            int row = (tid >> 3) + 32 * i;
            int p = pr[i];
            const float* src = x + (size_t)(p < 0 ? 0 : p) * DD + k0 + acol;
            cp16(sA_base + (st * STA + row * SA_STRIDE + acol) * 4, src, p >= 0);
        }
#pragma unroll
        for (int i = 0; i < 4; i++) {
            int idx = tid + i * 256;           // 0..1023
            int mat = idx >> 9;                // 0/1
            int r = (idx >> 4) & 31;
            int c4 = (idx & 15) * 4;
            const float* src = (mat ? B3p : B1p) + (size_t)(k0 + r) * FF + n0 + c4;
            cp16(sB_base + (((st * 2 + mat) * STB1) + r * SB1_STRIDE + c4) * 4, src, true);
        }
        cp_commit();
    };

    load_stage(0, 0);

    for (int k = 0; k < NK; k++) {
        int st = k & 1;
        if (k + 1 < NK) {
            load_stage(st ^ 1, (k + 1) * BK);
            asm volatile("cp.async.wait_group 1;\n");
        } else {
            asm volatile("cp.async.wait_group 0;\n");
        }
        __syncthreads();

        const float* A = sA + st * STA;
        const float* B1s = sB + (st * 2 + 0) * STB1;
        const float* B3s = sB + (st * 2 + 1) * STB1;
#pragma unroll
        for (int ks = 0; ks < BK; ks += 8) {
            uint32_t a[2][4];
#pragma unroll
            for (int mi = 0; mi < 2; mi++) {
                int rb = wm + mi * 16 + grp;
                a[mi][0] = f2tf(A[rb * SA_STRIDE + ks + qid]);
                a[mi][1] = f2tf(A[(rb + 8) * SA_STRIDE + ks + qid]);
                a[mi][2] = f2tf(A[rb * SA_STRIDE + ks + qid + 4]);
                a[mi][3] = f2tf(A[(rb + 8) * SA_STRIDE + ks + qid + 4]);
            }
#pragma unroll
            for (int ni = 0; ni < 4; ni++) {
                int cb = wn + ni * 8 + grp;
                uint32_t b1[2], b3[2];
                b1[0] = f2tf(B1s[(ks + qid) * SB1_STRIDE + cb]);
                b1[1] = f2tf(B1s[(ks + qid + 4) * SB1_STRIDE + cb]);
                b3[0] = f2tf(B3s[(ks + qid) * SB1_STRIDE + cb]);
                b3[1] = f2tf(B3s[(ks + qid + 4) * SB1_STRIDE + cb]);
#pragma unroll
                for (int mi = 0; mi < 2; mi++) {
                    mma_tf32(acc1[mi][ni], a[mi], b1);
                    mma_tf32(acc3[mi][ni], a[mi], b3);
                }
            }
        }
        __syncthreads();
    }

    // Epilogue: SwiGLU, pre-rounded to tf32 so ffn2 skips A-fragment cvt
#pragma unroll
    for (int mi = 0; mi < 2; mi++)
#pragma unroll
        for (int ni = 0; ni < 4; ni++)
#pragma unroll
            for (int t = 0; t < 4; t++) {
                int row = r0 + wm + mi * 16 + grp + ((t >= 2) ? 8 : 0);
                int col = n0 + wn + ni * 8 + qid * 2 + (t & 1);
                float a = acc1[mi][ni][t];
                float s = a / (1.f + expf(-a));
                g_h[(size_t)row * FF + col] = __uint_as_float(f2tf(s * acc3[mi][ni][t]));
            }
}

// ---------------------------------------------------------------------------
// FFN2: out[token] += wt * (h @ W2[e]); BN=128, cp.async pipeline, atomics.
__global__ __launch_bounds__(256, 2) void ffn2_kernel(
    const float* __restrict__ w2, float* __restrict__ out) {
    extern __shared__ float smem[];
    float* sA = smem;                 // [2][BM][SA_STRIDE]
    float* sB = smem + 2 * STA;       // [2][BK][SB2_STRIDE]

    const int NBT = DD / BN2;  // 8
    int bid = blockIdx.x;
    int strip = bid / (GROUP * NBT);
    int rem = bid % (GROUP * NBT);
    int tm = strip * GROUP + (rem % GROUP);
    int nb = rem / GROUP;
    if (tm >= MT) return;
    const int r0 = tm * BM;
    const int n0 = nb * BN2;
    if (r0 >= g_offs[NE]) return;

    int e = NE - 1;
#pragma unroll
    for (int i = 0; i < NE; i++)
        if (r0 >= g_offs[i] && r0 < g_offs[i + 1]) e = i;

    const float* Bp = w2 + (size_t)e * FF * DD;

    const int tid = threadIdx.x;
    const int lane = tid & 31, warp = tid >> 5;
    const int wm = (warp >> 1) * 32, wn = (warp & 1) * 64;
    const int grp = lane >> 2, qid = lane & 3;
    const int acol = (tid & 7) * 4;

    uint32_t sA_base = (uint32_t)__cvta_generic_to_shared(sA);
    uint32_t sB_base = (uint32_t)__cvta_generic_to_shared(sB);

    float acc[2][8][4];
#pragma unroll
    for (int mi = 0; mi < 2; mi++)
#pragma unroll
        for (int ni = 0; ni < 8; ni++)
#pragma unroll
            for (int t = 0; t < 4; t++) acc[mi][ni][t] = 0.f;

    const int NK = FF / BK;  // 128

    auto load_stage = [&](int st, int k0) {
#pragma unroll
        for (int i = 0; i < 4; i++) {
            int row = (tid >> 3) + 32 * i;
            const float* src = g_h + (size_t)(r0 + row) * FF + k0 + acol;
            cp16(sA_base + (st * STA + row * SA_STRIDE + acol) * 4, src, true);
        }
#pragma unroll
        for (int i = 0; i < 4; i++) {
            int idx = tid + i * 256;           // 0..1023
            int r = idx >> 5;
            int c4 = (idx & 31) * 4;
            const float* src = Bp + (size_t)(k0 + r) * DD + n0 + c4;
            cp16(sB_base + (st * STB2 + r * SB2_STRIDE + c4) * 4, src, true);
        }
        cp_commit();
    };

    load_stage(0, 0);

    for (int k = 0; k < NK; k++) {
        int st = k & 1;
        if (k + 1 < NK) {
            load_stage(st ^ 1, (k + 1) * BK);
            asm volatile("cp.async.wait_group 1;\n");
        } else {
            asm volatile("cp.async.wait_group 0;\n");
        }
        __syncthreads();

        const float* A = sA + st * STA;
        const float* Bs = sB + st * STB2;
#pragma unroll
        for (int ks = 0; ks < BK; ks += 8) {
            uint32_t a[2][4];
#pragma unroll
            for (int mi = 0; mi < 2; mi++) {
                int rb = wm + mi * 16 + grp;
                // g_h was stored pre-rounded to tf32: use raw bits directly
                a[mi][0] = __float_as_uint(A[rb * SA_STRIDE + ks + qid]);
                a[mi][1] = __float_as_uint(A[(rb + 8) * SA_STRIDE + ks + qid]);
                a[mi][2] = __float_as_uint(A[rb * SA_STRIDE + ks + qid + 4]);
                a[mi][3] = __float_as_uint(A[(rb + 8) * SA_STRIDE + ks + qid + 4]);
            }
#pragma unroll
            for (int ni = 0; ni < 8; ni++) {
                int cb = wn + ni * 8 + grp;
                uint32_t b[2];
                b[0] = f2tf(Bs[(ks + qid) * SB2_STRIDE + cb]);
                b[1] = f2tf(Bs[(ks + qid + 4) * SB2_STRIDE + cb]);
#pragma unroll
                for (int mi = 0; mi < 2; mi++) mma_tf32(acc[mi][ni], a[mi], b);
            }
        }
        __syncthreads();
    }

#pragma unroll
    for (int mi = 0; mi < 2; mi++) {
#pragma unroll
        for (int t2 = 0; t2 < 2; t2++) {
            int row = r0 + wm + mi * 16 + grp + t2 * 8;
            int p = g_perm[row];
            if (p < 0) continue;
            float w = g_wt[row];
#pragma unroll
            for (int ni = 0; ni < 8; ni++) {
#pragma unroll
                for (int t = 0; t < 2; t++) {
                    int col = n0 + wn + ni * 8 + qid * 2 + t;
                    atomicAdd(out + (size_t)p * DD + col, acc[mi][ni][t2 * 2 + t] * w);
                }
            }
        }
    }
}

// ---------------------------------------------------------------------------
extern "C" void kernel_launch(void* const* d_in, const int* in_sizes, int n_in,
                              void* d_out, int out_size) {
    const float* x  = (const float*)d_in[0];
    const float* gw = (const float*)d_in[1];
    const float* w1 = (const float*)d_in[2];
    const float* w3 = (const float*)d_in[3];
    const float* w2 = (const float*)d_in[4];
    float* out = (float*)d_out;

    cudaFuncSetAttribute(ffn1_kernel, cudaFuncAttributeMaxDynamicSharedMemorySize, SMEM1_BYTES);
    cudaFuncSetAttribute(ffn2_kernel, cudaFuncAttributeMaxDynamicSharedMemorySize, SMEM2_BYTES);

    init_kernel<<<4096, 256>>>(out);
    router_kernel<<<NT / 8, 256>>>(x, gw);
    offsets_kernel<<<1, 1>>>();
    scatter_kernel<<<(NT + 255) / 256, 256>>>();
    ffn1_kernel<<<MTP * (FF / BN1), 256, SMEM1_BYTES>>>(x, w1, w3);
    ffn2_kernel<<<MTP * (DD / BN2), 256, SMEM2_BYTES>>>(w2, out);
}